// round 9
// baseline (speedup 1.0000x reference)
#include <cuda_runtime.h>
#include <cuda_fp16.h>
#include <math.h>
#include <stdint.h>

#define SCALE 0.088388347648318447f  // 1/sqrt(128)

// ---- static scratch (allocation-free), fp16 intermediates ----
__device__ __half g_K  [16777216];   // [b,h,j,d]
__device__ __half g_Vt [16777216];   // [b,h,d,j]
__device__ __half g_QU [8388608];    // [b,h,i,d]  q+u
__device__ __half g_QV [8388608];    // [b,h,i,d]  q+v
__device__ __half g_P  [1048576];    // [h,jj,d]
__device__ __half g_S2 [67108864];   // [bh,i,j]   shifted position scores (valid j<=i+512)
__device__ __half g_O  [8388608];    // [i*B+b, h*128+d]
__device__ float  g_PE [131072];     // [jj,e]

__global__ void pe_fill() {
    int idx = blockIdx.x * blockDim.x + threadIdx.x;
    if (idx >= 65536) return;
    int jj = idx >> 6, e2 = idx & 63;
    double pos  = (double)(1023 - jj);
    double invf = exp(-((double)e2 / 64.0) * log(10000.0));
    double ang  = pos * invf;
    g_PE[jj * 128 + e2]      = (float)sin(ang);
    g_PE[jj * 128 + 64 + e2] = (float)cos(ang);
}

__device__ __forceinline__ uint32_t f2h2(float a, float b) {
    __half2 h = __floats2half2_rn(a, b);
    return *reinterpret_cast<uint32_t*>(&h);
}
__device__ __forceinline__ void ldsm4(uint32_t& r0, uint32_t& r1, uint32_t& r2, uint32_t& r3, uint32_t addr) {
    asm volatile("ldmatrix.sync.aligned.m8n8.x4.shared.b16 {%0,%1,%2,%3}, [%4];"
                 : "=r"(r0), "=r"(r1), "=r"(r2), "=r"(r3) : "r"(addr));
}
__device__ __forceinline__ void mma16(float* c, const uint32_t* a, uint32_t b0, uint32_t b1) {
    asm volatile("mma.sync.aligned.m16n8k16.row.col.f32.f16.f16.f32 "
                 "{%0,%1,%2,%3},{%4,%5,%6,%7},{%8,%9},{%0,%1,%2,%3};"
                 : "+f"(c[0]), "+f"(c[1]), "+f"(c[2]), "+f"(c[3])
                 : "r"(a[0]), "r"(a[1]), "r"(a[2]), "r"(a[3]), "r"(b0), "r"(b1));
}
__device__ __forceinline__ void cpa16(uint32_t saddr, const void* gptr) {
    asm volatile("cp.async.cg.shared.global [%0], [%1], 16;" :: "r"(saddr), "l"(gptr));
}
__device__ __forceinline__ void cp_commit() { asm volatile("cp.async.commit_group;"); }
template<int N> __device__ __forceinline__ void cp_wait() { asm volatile("cp.async.wait_group %0;" :: "n"(N)); }

// ---- fp16 tensor-core NT GEMM: C[M,N] = A[M,K] * W[N,K]^T ----
// BM=128, BN=64, BK=64 halves; 8 warps, each 32x32 via m16n8k16.
// Double-buffered smem, ONE barrier per K-iter.
// MODE 0: kv proj  1: q proj  2: p proj  4: pos scores (rel-shift epilogue)  6: out proj
template<int MODE>
__global__ void __launch_bounds__(256) gemm_k(
    const float* __restrict__ inputs, const float* __restrict__ mem0,
    const float* __restrict__ Wext, const float* __restrict__ uu,
    const float* __restrict__ vv, float* __restrict__ dout, int writeAux)
{
    constexpr int K   = (MODE >= 5) ? 1024 : 128;  // elements
    constexpr int KIT = K / 64;
    constexpr bool AF32 = (MODE <= 2);
    constexpr bool BF32 = (MODE <= 2 || MODE == 6);
    const int z  = blockIdx.z;
    const int m0 = blockIdx.y * 128, n0 = blockIdx.x * 64;
    if (MODE == 4 && m0 + n0 + 190 < 511) return;  // fully outside used band
    const int tid = threadIdx.x;
    const int lane = tid & 31, w = tid >> 5;
    const int wm = w >> 1, wn = w & 1;

    const float* Af = nullptr;
    const __half* Ah = nullptr;
    const float* Bf = Wext;
    const __half* Bh = nullptr;
    if (MODE == 1) Af = inputs;
    if (MODE == 2) Af = g_PE;
    if (MODE == 4) { Ah = g_QV + (size_t)z * 65536;  Bh = g_P + (size_t)(z & 7) * 131072; }
    if (MODE == 6) { Ah = g_O; }

    __shared__ uint32_t As[2][4096];
    __shared__ uint32_t Bs[2][2048];
    uint32_t as_addr = (uint32_t)__cvta_generic_to_shared(As);
    uint32_t bs_addr = (uint32_t)__cvta_generic_to_shared(Bs);

    float acc[2][4][4];
#pragma unroll
    for (int a = 0; a < 2; ++a)
#pragma unroll
        for (int b = 0; b < 4; ++b)
#pragma unroll
            for (int c = 0; c < 4; ++c) acc[a][b][c] = 0.f;

    float4 pa32[4][2], pb32[2][2];
    uint4 pa16[4], pb16[2];

    auto loadA = [&](int it) {
#pragma unroll
        for (int i = 0; i < 4; ++i) {
            int idx = tid + i * 256;
            int row = idx >> 3, ch = idx & 7;
            int r = m0 + row;
            if (AF32) {
                const float* Ap;
                if (MODE == 0)
                    Ap = (r < 8192) ? (mem0 + (size_t)r * 128)
                                    : (inputs + (size_t)(r - 8192) * 128);
                else
                    Ap = Af + (size_t)r * K;
                pa32[i][0] = *(const float4*)(Ap + it * 64 + ch * 8);
                pa32[i][1] = *(const float4*)(Ap + it * 64 + ch * 8 + 4);
            } else {
                pa16[i] = *(const uint4*)(Ah + (size_t)r * K + it * 64 + ch * 8);
            }
        }
    };
    auto loadB = [&](int it) {
#pragma unroll
        for (int i = 0; i < 2; ++i) {
            int idx = tid + i * 256;
            int row = idx >> 3, ch = idx & 7;
            if (BF32) {
                pb32[i][0] = *(const float4*)(Bf + (size_t)(n0 + row) * K + it * 64 + ch * 8);
                pb32[i][1] = *(const float4*)(Bf + (size_t)(n0 + row) * K + it * 64 + ch * 8 + 4);
            } else {
                pb16[i] = *(const uint4*)(Bh + (size_t)(n0 + row) * K + it * 64 + ch * 8);
            }
        }
    };
    auto stage = [&](int s) {
#pragma unroll
        for (int i = 0; i < 4; ++i) {
            int idx = tid + i * 256;
            int row = idx >> 3, ch = idx & 7;
            uint32_t off = row * 32 + ((ch ^ (row & 7)) << 2);
            uint4 v;
            if (AF32) v = make_uint4(f2h2(pa32[i][0].x, pa32[i][0].y), f2h2(pa32[i][0].z, pa32[i][0].w),
                                     f2h2(pa32[i][1].x, pa32[i][1].y), f2h2(pa32[i][1].z, pa32[i][1].w));
            else v = pa16[i];
            *(uint4*)&As[s][off] = v;
        }
#pragma unroll
        for (int i = 0; i < 2; ++i) {
            int idx = tid + i * 256;
            int row = idx >> 3, ch = idx & 7;
            uint32_t off = row * 32 + ((ch ^ (row & 7)) << 2);
            uint4 v;
            if (BF32) v = make_uint4(f2h2(pb32[i][0].x, pb32[i][0].y), f2h2(pb32[i][0].z, pb32[i][0].w),
                                     f2h2(pb32[i][1].x, pb32[i][1].y), f2h2(pb32[i][1].z, pb32[i][1].w));
            else v = pb16[i];
            *(uint4*)&Bs[s][off] = v;
        }
    };

    loadA(0); loadB(0);
    stage(0);
    __syncthreads();

    const int lrow = lane & 7, lm = lane >> 3;
    for (int it = 0; it < KIT; ++it) {
        const int s = it & 1;
        if (it + 1 < KIT) { loadA(it + 1); loadB(it + 1); }
#pragma unroll
        for (int ks = 0; ks < 4; ++ks) {  // k16 steps within BK=64
            uint32_t afr[2][4], bfr[2][4];
#pragma unroll
            for (int mi = 0; mi < 2; ++mi) {
                int row = wm * 32 + mi * 16 + ((lm & 1) << 3) + lrow;
                int ch  = ks * 2 + (lm >> 1);
                ldsm4(afr[mi][0], afr[mi][1], afr[mi][2], afr[mi][3],
                      as_addr + ((s * 4096 + row * 32 + ((ch ^ lrow) << 2)) << 2));
            }
#pragma unroll
            for (int np = 0; np < 2; ++np) {
                int row = wn * 32 + np * 16 + ((lm >> 1) << 3) + lrow;
                int ch  = ks * 2 + (lm & 1);
                ldsm4(bfr[np][0], bfr[np][1], bfr[np][2], bfr[np][3],
                      bs_addr + ((s * 2048 + row * 32 + ((ch ^ lrow) << 2)) << 2));
            }
#pragma unroll
            for (int mi = 0; mi < 2; ++mi)
#pragma unroll
                for (int nj = 0; nj < 4; ++nj)
                    mma16(acc[mi][nj], afr[mi], bfr[nj >> 1][(nj & 1) * 2], bfr[nj >> 1][(nj & 1) * 2 + 1]);
        }
        if (it + 1 < KIT) { stage(s ^ 1); __syncthreads(); }
    }

    // ---- epilogue ----
    const int r0l = lane >> 2, c0l = (lane & 3) * 2;
#pragma unroll
    for (int mi = 0; mi < 2; ++mi)
#pragma unroll
        for (int nj = 0; nj < 4; ++nj)
#pragma unroll
            for (int e = 0; e < 4; ++e) {
                int r = m0 + wm * 32 + mi * 16 + r0l + ((e >= 2) ? 8 : 0);
                int n = n0 + wn * 32 + nj * 8 + c0l + (e & 1);
                float val = acc[mi][nj][e];
                if (MODE == 0) {
                    int j = r >> 4, b = r & 15;
                    if (n < 1024) {
                        int h = n >> 7, d = n & 127;
                        g_K[(size_t)((b * 8 + h) * 1024 + j) * 128 + d] = __float2half(val);
                    } else {
                        int n2 = n - 1024; int h = n2 >> 7, d = n2 & 127;
                        g_Vt[(size_t)((b * 8 + h) * 128 + d) * 1024 + j] = __float2half(val);
                    }
                } else if (MODE == 1) {
                    int i = r >> 4, b = r & 15;
                    size_t base = (size_t)((b * 8 + (n >> 7)) * 512 + i) * 128 + (n & 127);
                    g_QU[base] = __float2half(val + uu[n]);
                    g_QV[base] = __float2half(val + vv[n]);
                } else if (MODE == 2) {
                    g_P[(size_t)((n >> 7) * 1024 + r) * 128 + (n & 127)] = __float2half(val);
                } else if (MODE == 4) {
                    int j = n - 511 + r;  // rel-shift: S2shift[i][j] = S2[i][511+j-i]
                    if (j >= 0 && j < 1024)
                        g_S2[(size_t)z * 524288 + (size_t)r * 1024 + j] = __float2half(val);
                } else {  // MODE 6
                    dout[(size_t)r * 128 + n] = val;
                    if (writeAux) dout[2097152 + (size_t)r * 128 + n] = val;
                }
            }
}

// ---- fused flash attention (fp16): S = QK^T + S2shift, fixed-base softmax, O = P V ----
// 3-stage cp.async pipeline (K,V,S2), ONE barrier per jt, no online-max rescale
// (scores are O(0.3) after SCALE: exp without max-subtraction is exact-safe in fp32).
__global__ void __launch_bounds__(256, 1) flash_k() {
    extern __shared__ uint32_t sm[];
    // per stage (12288 u32): K at +0 (2 segs x 2048), V at +4096, S2 at +8192
    uint32_t* sP = sm + 36864;     // 128 i-rows x 32 u32
    const uint32_t smb = (uint32_t)__cvta_generic_to_shared(sm);
    const uint32_t sPb = (uint32_t)__cvta_generic_to_shared(sP);

    const int bh = blockIdx.y;
    const int ix = 3 - blockIdx.x;     // heavy tiles launch first
    const int i0 = ix * 128;
    const int tid = threadIdx.x, lane = tid & 31, w = tid >> 5;
    const int lrow = lane & 7, lm = lane >> 3;
    const int r0l = lane >> 2, c0l = (lane & 3) * 2;

    const __half* Qb  = g_QU + (size_t)bh * 65536;
    const __half* Kb  = g_K  + (size_t)bh * 131072;
    const __half* Vb  = g_Vt + (size_t)bh * 131072;
    const __half* S2b = g_S2 + (size_t)bh * 524288;

    uint32_t qf[8][4];

    // ---- Q fragments via smem staging (stage-0 K region, two 64-row halves) ----
#pragma unroll
    for (int half = 0; half < 2; ++half) {
#pragma unroll
        for (int t = 0; t < 4; ++t) {
            int idx = tid + t * 256;
            int row = idx >> 4, c16 = idx & 15;
            int seg = c16 >> 3, ch = c16 & 7;
            uint4 v = *(const uint4*)(Qb + (size_t)(i0 + half * 64 + row) * 128 + c16 * 8);
            *(uint4*)&sm[seg * 2048 + row * 32 + ((ch ^ (row & 7)) << 2)] = v;
        }
        __syncthreads();
        if ((w >> 2) == half) {
            int wr = (w & 3) * 16;
#pragma unroll
            for (int ks = 0; ks < 8; ++ks) {
                int row = wr + ((lm & 1) << 3) + lrow;
                int seg = ks >> 2, ch = (ks & 3) * 2 + (lm >> 1);
                ldsm4(qf[ks][0], qf[ks][1], qf[ks][2], qf[ks][3],
                      smb + ((seg * 2048 + row * 32 + ((ch ^ lrow) << 2)) << 2));
            }
        }
        __syncthreads();
    }

    // cp.async prefetch of one jt tile (K 16KB + V 16KB + S2 16KB) into stage s
    auto pref = [&](int jt, int s) {
        int j0 = jt * 64;
        int sb = s * 12288;
#pragma unroll
        for (int t = 0; t < 4; ++t) {
            int idx = tid + t * 256;
            int row = idx >> 4, c16 = idx & 15;
            int seg = c16 >> 3, ch = c16 & 7;
            cpa16(smb + ((sb + seg * 2048 + row * 32 + ((ch ^ (row & 7)) << 2)) << 2),
                  Kb + (size_t)(j0 + row) * 128 + c16 * 8);
        }
#pragma unroll
        for (int t = 0; t < 4; ++t) {
            int idx = tid + t * 256;
            int row = idx >> 3, ch = idx & 7;
            cpa16(smb + ((sb + 4096 + row * 32 + ((ch ^ (row & 7)) << 2)) << 2),
                  Vb + (size_t)row * 1024 + j0 + ch * 8);
        }
#pragma unroll
        for (int t = 0; t < 4; ++t) {
            int idx = tid + t * 256;
            int row = idx >> 3, ch = idx & 7;
            cpa16(smb + ((sb + 8192 + row * 32 + ((ch ^ (row & 7)) << 2)) << 2),
                  S2b + (size_t)(i0 + row) * 1024 + j0 + ch * 8);
        }
    };

    float of[16][4];
#pragma unroll
    for (int a = 0; a < 16; ++a)
#pragma unroll
        for (int e = 0; e < 4; ++e) of[a][e] = 0.f;
    float lrow0 = 0.f, lrow1 = 0.f;   // per-lane partial row sums (reduced after loop)

    const int gi0 = i0 + w * 16 + r0l;
    const int gi1 = gi0 + 8;
    const int lr0 = w * 16 + r0l, lr1 = lr0 + 8;  // local rows in sS2
    const int njt = 2 * ix + 10;

    pref(0, 0); cp_commit();
    pref(1, 1); cp_commit();

    int s = 0;
    for (int jt = 0; jt < njt; ++jt) {
        int j0 = jt * 64;
        if (jt + 1 < njt) cp_wait<1>(); else cp_wait<0>();
        __syncthreads();
        if (jt + 2 < njt) {
            int s2 = s + 2; if (s2 >= 3) s2 -= 3;
            pref(jt + 2, s2); cp_commit();
        }
        const int sb = s * 12288;

        // scores: S = Q K^T (16 x 64 per warp)
        float sacc[8][4];
#pragma unroll
        for (int a = 0; a < 8; ++a)
#pragma unroll
            for (int e = 0; e < 4; ++e) sacc[a][e] = 0.f;
#pragma unroll
        for (int ks = 0; ks < 8; ++ks) {
            uint32_t bfr[4][4];
#pragma unroll
            for (int nb = 0; nb < 4; ++nb) {
                int row = nb * 16 + ((lm >> 1) << 3) + lrow;
                int seg = ks >> 2, ch = (ks & 3) * 2 + (lm & 1);
                ldsm4(bfr[nb][0], bfr[nb][1], bfr[nb][2], bfr[nb][3],
                      smb + ((sb + seg * 2048 + row * 32 + ((ch ^ lrow) << 2)) << 2));
            }
#pragma unroll
            for (int nf = 0; nf < 8; ++nf)
                mma16(sacc[nf], qf[ks], bfr[nf >> 1][(nf & 1) * 2], bfr[nf >> 1][(nf & 1) * 2 + 1]);
        }

        // add shifted position scores (smem), scale, exp (fixed base), mask, accumulate sums
#pragma unroll
        for (int nf = 0; nf < 8; ++nf) {
            int jc = j0 + nf * 8 + c0l;
            uint32_t u0 = sm[sb + 8192 + lr0 * 32 + ((nf ^ r0l) << 2) + (lane & 3)];
            uint32_t u1 = sm[sb + 8192 + lr1 * 32 + ((nf ^ r0l) << 2) + (lane & 3)];
            float2 p0 = __half22float2(*reinterpret_cast<__half2*>(&u0));
            float2 p1 = __half22float2(*reinterpret_cast<__half2*>(&u1));
            float e00 = (jc     <= gi0 + 512) ? __expf((sacc[nf][0] + p0.x) * SCALE) : 0.f;
            float e01 = (jc + 1 <= gi0 + 512) ? __expf((sacc[nf][1] + p0.y) * SCALE) : 0.f;
            float e10 = (jc     <= gi1 + 512) ? __expf((sacc[nf][2] + p1.x) * SCALE) : 0.f;
            float e11 = (jc + 1 <= gi1 + 512) ? __expf((sacc[nf][3] + p1.y) * SCALE) : 0.f;
            lrow0 += e00 + e01;
            lrow1 += e10 + e11;
            // store P to warp-private sP rows (fp16 pairs, swizzled)
            int c  = nf * 8 + c0l;
            int ch = c >> 3, wi = (c >> 1) & 3;
            int row0 = w * 16 + r0l;
            sP[row0 * 32 + ((ch ^ (row0 & 7)) << 2) + wi] = f2h2(e00, e01);
            int row1 = row0 + 8;
            sP[row1 * 32 + ((ch ^ (row1 & 7)) << 2) + wi] = f2h2(e10, e11);
        }
        __syncwarp();

        // O += P V^T
#pragma unroll
        for (int ks = 0; ks < 4; ++ks) {
            uint32_t pa[4];
            {
                int row = w * 16 + ((lm & 1) << 3) + lrow;
                int ch  = ks * 2 + (lm >> 1);
                ldsm4(pa[0], pa[1], pa[2], pa[3],
                      sPb + ((row * 32 + ((ch ^ lrow) << 2)) << 2));
            }
#pragma unroll
            for (int nb = 0; nb < 8; ++nb) {
                uint32_t bv[4];
                int rowb = nb * 16 + ((lm >> 1) << 3) + lrow;
                int chb  = ks * 2 + (lm & 1);
                ldsm4(bv[0], bv[1], bv[2], bv[3],
                      smb + ((sb + 4096 + rowb * 32 + ((chb ^ lrow) << 2)) << 2));
                mma16(of[nb * 2],     pa, bv[0], bv[1]);
                mma16(of[nb * 2 + 1], pa, bv[2], bv[3]);
            }
        }
        if (++s == 3) s = 0;
    }

    // reduce row sums across the quad (cols are spread over 4 lanes)
    lrow0 += __shfl_xor_sync(0xffffffffu, lrow0, 1);
    lrow0 += __shfl_xor_sync(0xffffffffu, lrow0, 2);
    lrow1 += __shfl_xor_sync(0xffffffffu, lrow1, 1);
    lrow1 += __shfl_xor_sync(0xffffffffu, lrow1, 2);

    // normalize + write O (fp16)
    float inv0 = 1.f / lrow0, inv1 = 1.f / lrow1;
    int b = bh >> 3, h = bh & 7;
#pragma unroll
    for (int nf = 0; nf < 16; ++nf) {
        int d = nf * 8 + c0l;
        *(uint32_t*)&g_O[(size_t)(gi0 * 16 + b) * 1024 + h * 128 + d] = f2h2(of[nf][0] * inv0, of[nf][1] * inv0);
        *(uint32_t*)&g_O[(size_t)(gi1 * 16 + b) * 1024 + h * 128 + d] = f2h2(of[nf][2] * inv1, of[nf][3] * inv1);
    }
}

__global__ void copy_k(const float* __restrict__ src, float* __restrict__ dst) {
    int idx = blockIdx.x * blockDim.x + threadIdx.x;
    ((float4*)dst)[idx] = ((const float4*)src)[idx];
}

extern "C" void kernel_launch(void* const* d_in, const int* in_sizes, int n_in,
                              void* d_out, int out_size) {
    const float* inputs = (const float*)d_in[0];
    const float* memory = (const float*)d_in[1];
    const float* w_kv   = (const float*)d_in[2];
    const float* w_q    = (const float*)d_in[3];
    const float* w_p    = (const float*)d_in[4];
    const float* w_out  = (const float*)d_in[5];
    const float* u      = (const float*)d_in[6];
    const float* v      = (const float*)d_in[7];
    float* out = (float*)d_out;

    int writeAux = (out_size >= 3 * 1048576) ? 1 : 0;

    cudaFuncSetAttribute(flash_k, cudaFuncAttributeMaxDynamicSharedMemorySize, 163840);

    pe_fill<<<256, 256>>>();
    // kv proj: M=16384, N=2048, K=128
    gemm_k<0><<<dim3(32, 128, 1), 256>>>(inputs, memory, w_kv, nullptr, nullptr, nullptr, 0);
    // q proj: M=8192, N=1024, K=128
    gemm_k<1><<<dim3(16, 64, 1), 256>>>(inputs, nullptr, w_q, u, v, nullptr, 0);
    // p proj: M=1024, N=1024, K=128
    gemm_k<2><<<dim3(16, 8, 1), 256>>>(inputs, nullptr, w_p, nullptr, nullptr, nullptr, 0);
    // position scores (shifted epilogue): M=512, N=1024, K=128, z=128
    gemm_k<4><<<dim3(16, 4, 128), 256>>>(inputs, nullptr, nullptr, nullptr, nullptr, nullptr, 0);
    // fused flash attention (3-stage cp.async, fixed-base softmax)
    flash_k<<<dim3(4, 128), 256, 163840>>>();
    // out proj: M=8192, N=128, K=1024
    gemm_k<6><<<dim3(2, 64), 256>>>(inputs, nullptr, w_out, nullptr, nullptr, out, writeAux);
    if (writeAux) copy_k<<<1024, 256>>>(inputs, out + 1048576);
}

// round 10
// speedup vs baseline: 1.0505x; 1.0505x over previous
#include <cuda_runtime.h>
#include <cuda_fp16.h>
#include <math.h>
#include <stdint.h>

#define SCALE 0.088388347648318447f  // 1/sqrt(128)

// ---- static scratch (allocation-free), fp16 intermediates ----
__device__ __half g_K  [16777216];   // [b,h,j,d]
__device__ __half g_Vt [16777216];   // [b,h,d,j]
__device__ __half g_QU [8388608];    // [b,h,i,d]  q+u
__device__ __half g_QV [8388608];    // [b,h,i,d]  q+v
__device__ __half g_P  [1048576];    // [h,jj,d]
__device__ __half g_S2 [67108864];   // [bh,i,j]   shifted position scores (valid j<=i+512)
__device__ __half g_O  [8388608];    // [i*B+b, h*128+d]
__device__ float  g_PE [131072];     // [jj,e]

__global__ void pe_fill() {
    int idx = blockIdx.x * blockDim.x + threadIdx.x;
    if (idx >= 65536) return;
    int jj = idx >> 6, e2 = idx & 63;
    double pos  = (double)(1023 - jj);
    double invf = exp(-((double)e2 / 64.0) * log(10000.0));
    double ang  = pos * invf;
    g_PE[jj * 128 + e2]      = (float)sin(ang);
    g_PE[jj * 128 + 64 + e2] = (float)cos(ang);
}

__device__ __forceinline__ uint32_t f2h2(float a, float b) {
    __half2 h = __floats2half2_rn(a, b);
    return *reinterpret_cast<uint32_t*>(&h);
}
__device__ __forceinline__ void ldsm4(uint32_t& r0, uint32_t& r1, uint32_t& r2, uint32_t& r3, uint32_t addr) {
    asm volatile("ldmatrix.sync.aligned.m8n8.x4.shared.b16 {%0,%1,%2,%3}, [%4];"
                 : "=r"(r0), "=r"(r1), "=r"(r2), "=r"(r3) : "r"(addr));
}
__device__ __forceinline__ void mma16(float* c, const uint32_t* a, uint32_t b0, uint32_t b1) {
    asm volatile("mma.sync.aligned.m16n8k16.row.col.f32.f16.f16.f32 "
                 "{%0,%1,%2,%3},{%4,%5,%6,%7},{%8,%9},{%0,%1,%2,%3};"
                 : "+f"(c[0]), "+f"(c[1]), "+f"(c[2]), "+f"(c[3])
                 : "r"(a[0]), "r"(a[1]), "r"(a[2]), "r"(a[3]), "r"(b0), "r"(b1));
}
__device__ __forceinline__ void cpa16(uint32_t saddr, const void* gptr) {
    asm volatile("cp.async.cg.shared.global [%0], [%1], 16;" :: "r"(saddr), "l"(gptr));
}
__device__ __forceinline__ void cp_commit() { asm volatile("cp.async.commit_group;"); }
template<int N> __device__ __forceinline__ void cp_wait() { asm volatile("cp.async.wait_group %0;" :: "n"(N)); }

// ---- fp16 tensor-core NT GEMM: C[M,N] = A[M,K] * W[N,K]^T ----
// BM=128, BN=64, BK=64 halves; 8 warps, each 32x32 via m16n8k16.
// Double-buffered smem, ONE barrier per K-iter. 2 CTAs/SM forced.
// MODE 0: kv proj  1: q proj  2: p proj  4: pos scores (rel-shift epilogue)  6: out proj
template<int MODE>
__global__ void __launch_bounds__(256, 2) gemm_k(
    const float* __restrict__ inputs, const float* __restrict__ mem0,
    const float* __restrict__ Wext, const float* __restrict__ uu,
    const float* __restrict__ vv, float* __restrict__ dout, int writeAux)
{
    constexpr int K   = (MODE >= 5) ? 1024 : 128;  // elements
    constexpr int KIT = K / 64;
    constexpr bool AF32 = (MODE <= 2);
    constexpr bool BF32 = (MODE <= 2 || MODE == 6);
    const int z  = blockIdx.z;
    const int m0 = blockIdx.y * 128, n0 = blockIdx.x * 64;
    if (MODE == 4 && m0 + n0 + 190 < 511) return;  // fully outside used band
    const int tid = threadIdx.x;
    const int lane = tid & 31, w = tid >> 5;
    const int wm = w >> 1, wn = w & 1;

    const float* Af = nullptr;
    const __half* Ah = nullptr;
    const float* Bf = Wext;
    const __half* Bh = nullptr;
    if (MODE == 1) Af = inputs;
    if (MODE == 2) Af = g_PE;
    if (MODE == 4) { Ah = g_QV + (size_t)z * 65536;  Bh = g_P + (size_t)(z & 7) * 131072; }
    if (MODE == 6) { Ah = g_O; }

    __shared__ uint32_t As[2][4096];
    __shared__ uint32_t Bs[2][2048];
    uint32_t as_addr = (uint32_t)__cvta_generic_to_shared(As);
    uint32_t bs_addr = (uint32_t)__cvta_generic_to_shared(Bs);

    float acc[2][4][4];
#pragma unroll
    for (int a = 0; a < 2; ++a)
#pragma unroll
        for (int b = 0; b < 4; ++b)
#pragma unroll
            for (int c = 0; c < 4; ++c) acc[a][b][c] = 0.f;

    float4 pa32[4][2], pb32[2][2];
    uint4 pa16[4], pb16[2];

    auto loadA = [&](int it) {
#pragma unroll
        for (int i = 0; i < 4; ++i) {
            int idx = tid + i * 256;
            int row = idx >> 3, ch = idx & 7;
            int r = m0 + row;
            if (AF32) {
                const float* Ap;
                if (MODE == 0)
                    Ap = (r < 8192) ? (mem0 + (size_t)r * 128)
                                    : (inputs + (size_t)(r - 8192) * 128);
                else
                    Ap = Af + (size_t)r * K;
                pa32[i][0] = *(const float4*)(Ap + it * 64 + ch * 8);
                pa32[i][1] = *(const float4*)(Ap + it * 64 + ch * 8 + 4);
            } else {
                pa16[i] = *(const uint4*)(Ah + (size_t)r * K + it * 64 + ch * 8);
            }
        }
    };
    auto loadB = [&](int it) {
#pragma unroll
        for (int i = 0; i < 2; ++i) {
            int idx = tid + i * 256;
            int row = idx >> 3, ch = idx & 7;
            if (BF32) {
                pb32[i][0] = *(const float4*)(Bf + (size_t)(n0 + row) * K + it * 64 + ch * 8);
                pb32[i][1] = *(const float4*)(Bf + (size_t)(n0 + row) * K + it * 64 + ch * 8 + 4);
            } else {
                pb16[i] = *(const uint4*)(Bh + (size_t)(n0 + row) * K + it * 64 + ch * 8);
            }
        }
    };
    auto stage = [&](int s) {
#pragma unroll
        for (int i = 0; i < 4; ++i) {
            int idx = tid + i * 256;
            int row = idx >> 3, ch = idx & 7;
            uint32_t off = row * 32 + ((ch ^ (row & 7)) << 2);
            uint4 v;
            if (AF32) v = make_uint4(f2h2(pa32[i][0].x, pa32[i][0].y), f2h2(pa32[i][0].z, pa32[i][0].w),
                                     f2h2(pa32[i][1].x, pa32[i][1].y), f2h2(pa32[i][1].z, pa32[i][1].w));
            else v = pa16[i];
            *(uint4*)&As[s][off] = v;
        }
#pragma unroll
        for (int i = 0; i < 2; ++i) {
            int idx = tid + i * 256;
            int row = idx >> 3, ch = idx & 7;
            uint32_t off = row * 32 + ((ch ^ (row & 7)) << 2);
            uint4 v;
            if (BF32) v = make_uint4(f2h2(pb32[i][0].x, pb32[i][0].y), f2h2(pb32[i][0].z, pb32[i][0].w),
                                     f2h2(pb32[i][1].x, pb32[i][1].y), f2h2(pb32[i][1].z, pb32[i][1].w));
            else v = pb16[i];
            *(uint4*)&Bs[s][off] = v;
        }
    };

    loadA(0); loadB(0);
    stage(0);
    __syncthreads();

    const int lrow = lane & 7, lm = lane >> 3;
    for (int it = 0; it < KIT; ++it) {
        const int s = it & 1;
        if (it + 1 < KIT) { loadA(it + 1); loadB(it + 1); }
#pragma unroll
        for (int ks = 0; ks < 4; ++ks) {  // k16 steps within BK=64
            uint32_t afr[2][4], bfr[2][4];
#pragma unroll
            for (int mi = 0; mi < 2; ++mi) {
                int row = wm * 32 + mi * 16 + ((lm & 1) << 3) + lrow;
                int ch  = ks * 2 + (lm >> 1);
                ldsm4(afr[mi][0], afr[mi][1], afr[mi][2], afr[mi][3],
                      as_addr + ((s * 4096 + row * 32 + ((ch ^ lrow) << 2)) << 2));
            }
#pragma unroll
            for (int np = 0; np < 2; ++np) {
                int row = wn * 32 + np * 16 + ((lm >> 1) << 3) + lrow;
                int ch  = ks * 2 + (lm & 1);
                ldsm4(bfr[np][0], bfr[np][1], bfr[np][2], bfr[np][3],
                      bs_addr + ((s * 2048 + row * 32 + ((ch ^ lrow) << 2)) << 2));
            }
#pragma unroll
            for (int mi = 0; mi < 2; ++mi)
#pragma unroll
                for (int nj = 0; nj < 4; ++nj)
                    mma16(acc[mi][nj], afr[mi], bfr[nj >> 1][(nj & 1) * 2], bfr[nj >> 1][(nj & 1) * 2 + 1]);
        }
        if (it + 1 < KIT) { stage(s ^ 1); __syncthreads(); }
    }

    // ---- epilogue ----
    const int r0l = lane >> 2, c0l = (lane & 3) * 2;
#pragma unroll
    for (int mi = 0; mi < 2; ++mi)
#pragma unroll
        for (int nj = 0; nj < 4; ++nj)
#pragma unroll
            for (int e = 0; e < 4; ++e) {
                int r = m0 + wm * 32 + mi * 16 + r0l + ((e >= 2) ? 8 : 0);
                int n = n0 + wn * 32 + nj * 8 + c0l + (e & 1);
                float val = acc[mi][nj][e];
                if (MODE == 0) {
                    int j = r >> 4, b = r & 15;
                    if (n < 1024) {
                        int h = n >> 7, d = n & 127;
                        g_K[(size_t)((b * 8 + h) * 1024 + j) * 128 + d] = __float2half(val);
                    } else {
                        int n2 = n - 1024; int h = n2 >> 7, d = n2 & 127;
                        g_Vt[(size_t)((b * 8 + h) * 128 + d) * 1024 + j] = __float2half(val);
                    }
                } else if (MODE == 1) {
                    int i = r >> 4, b = r & 15;
                    size_t base = (size_t)((b * 8 + (n >> 7)) * 512 + i) * 128 + (n & 127);
                    g_QU[base] = __float2half(val + uu[n]);
                    g_QV[base] = __float2half(val + vv[n]);
                } else if (MODE == 2) {
                    g_P[(size_t)((n >> 7) * 1024 + r) * 128 + (n & 127)] = __float2half(val);
                } else if (MODE == 4) {
                    int j = n - 511 + r;  // rel-shift: S2shift[i][j] = S2[i][511+j-i]
                    if (j >= 0 && j < 1024)
                        g_S2[(size_t)z * 524288 + (size_t)r * 1024 + j] = __float2half(val);
                } else {  // MODE 6
                    dout[(size_t)r * 128 + n] = val;
                    if (writeAux) dout[2097152 + (size_t)r * 128 + n] = val;
                }
            }
}

// ---- fused flash attention (fp16): S = QK^T + S2shift, masked online softmax, O = P V ----
// K, V, S2 tiles double-buffered via cp.async: jt+1 loads overlap jt compute.
__global__ void __launch_bounds__(256, 1) flash_k() {
    extern __shared__ uint32_t sm[];
    uint32_t* sK  = sm;            // 2 bufs x [2 segs x 64 rows x 32 u32] : K tile / Q staging
    uint32_t* sV  = sm + 8192;     // 2 bufs x [128 d-rows x 32 u32]
    uint32_t* sS2 = sm + 16384;    // 2 bufs x [128 i-rows x 32 u32]
    uint32_t* sP  = sm + 24576;    // 128 i-rows x 32 u32
    const uint32_t sKb  = (uint32_t)__cvta_generic_to_shared(sK);
    const uint32_t sVb  = (uint32_t)__cvta_generic_to_shared(sV);
    const uint32_t sS2b = (uint32_t)__cvta_generic_to_shared(sS2);
    const uint32_t sPb  = (uint32_t)__cvta_generic_to_shared(sP);

    const int bh = blockIdx.y;
    const int ix = 3 - blockIdx.x;     // heavy tiles launch first
    const int i0 = ix * 128;
    const int tid = threadIdx.x, lane = tid & 31, w = tid >> 5;
    const int lrow = lane & 7, lm = lane >> 3;
    const int r0l = lane >> 2, c0l = (lane & 3) * 2;

    const __half* Qb  = g_QU + (size_t)bh * 65536;
    const __half* Kb  = g_K  + (size_t)bh * 131072;
    const __half* Vb  = g_Vt + (size_t)bh * 131072;
    const __half* S2b = g_S2 + (size_t)bh * 524288;

    uint32_t qf[8][4];

    // ---- Q fragments via smem staging (reuse sK buf0, two 64-row halves) ----
#pragma unroll
    for (int half = 0; half < 2; ++half) {
#pragma unroll
        for (int t = 0; t < 4; ++t) {
            int idx = tid + t * 256;
            int row = idx >> 4, c16 = idx & 15;
            int seg = c16 >> 3, ch = c16 & 7;
            uint4 v = *(const uint4*)(Qb + (size_t)(i0 + half * 64 + row) * 128 + c16 * 8);
            *(uint4*)&sK[seg * 2048 + row * 32 + ((ch ^ (row & 7)) << 2)] = v;
        }
        __syncthreads();
        if ((w >> 2) == half) {
            int wr = (w & 3) * 16;
#pragma unroll
            for (int ks = 0; ks < 8; ++ks) {
                int row = wr + ((lm & 1) << 3) + lrow;
                int seg = ks >> 2, ch = (ks & 3) * 2 + (lm >> 1);
                ldsm4(qf[ks][0], qf[ks][1], qf[ks][2], qf[ks][3],
                      sKb + ((seg * 2048 + row * 32 + ((ch ^ lrow) << 2)) << 2));
            }
        }
        __syncthreads();
    }

    // cp.async prefetch of one jt tile (K 16KB + V 16KB + S2 16KB) into buffer s
    auto pref = [&](int jt, int s) {
        int j0 = jt * 64;
#pragma unroll
        for (int t = 0; t < 4; ++t) {
            int idx = tid + t * 256;
            int row = idx >> 4, c16 = idx & 15;
            int seg = c16 >> 3, ch = c16 & 7;
            cpa16(sKb + ((s * 4096 + seg * 2048 + row * 32 + ((ch ^ (row & 7)) << 2)) << 2),
                  Kb + (size_t)(j0 + row) * 128 + c16 * 8);
        }
#pragma unroll
        for (int t = 0; t < 4; ++t) {
            int idx = tid + t * 256;
            int row = idx >> 3, ch = idx & 7;
            cpa16(sVb + ((s * 4096 + row * 32 + ((ch ^ (row & 7)) << 2)) << 2),
                  Vb + (size_t)row * 1024 + j0 + ch * 8);
        }
#pragma unroll
        for (int t = 0; t < 4; ++t) {
            int idx = tid + t * 256;
            int row = idx >> 3, ch = idx & 7;
            cpa16(sS2b + ((s * 4096 + row * 32 + ((ch ^ (row & 7)) << 2)) << 2),
                  S2b + (size_t)(i0 + row) * 1024 + j0 + ch * 8);
        }
    };

    float of[16][4];
#pragma unroll
    for (int a = 0; a < 16; ++a)
#pragma unroll
        for (int e = 0; e < 4; ++e) of[a][e] = 0.f;
    float mrow0 = -1e30f, mrow1 = -1e30f;
    float lrow0 = 0.f, lrow1 = 0.f;

    const int gi0 = i0 + w * 16 + r0l;
    const int gi1 = gi0 + 8;
    const int lr0 = w * 16 + r0l, lr1 = lr0 + 8;  // local rows in sS2
    const int njt = 2 * ix + 10;

    pref(0, 0); cp_commit();

    for (int jt = 0; jt < njt; ++jt) {
        const int s = jt & 1;
        int j0 = jt * 64;
        if (jt + 1 < njt) { pref(jt + 1, s ^ 1); cp_commit(); cp_wait<1>(); }
        else cp_wait<0>();
        __syncthreads();

        // scores: S = Q K^T (16 x 64 per warp)
        float sacc[8][4];
#pragma unroll
        for (int a = 0; a < 8; ++a)
#pragma unroll
            for (int e = 0; e < 4; ++e) sacc[a][e] = 0.f;
#pragma unroll
        for (int ks = 0; ks < 8; ++ks) {
            uint32_t bfr[4][4];
#pragma unroll
            for (int nb = 0; nb < 4; ++nb) {
                int row = nb * 16 + ((lm >> 1) << 3) + lrow;
                int seg = ks >> 2, ch = (ks & 3) * 2 + (lm & 1);
                ldsm4(bfr[nb][0], bfr[nb][1], bfr[nb][2], bfr[nb][3],
                      sKb + ((s * 4096 + seg * 2048 + row * 32 + ((ch ^ lrow) << 2)) << 2));
            }
#pragma unroll
            for (int nf = 0; nf < 8; ++nf)
                mma16(sacc[nf], qf[ks], bfr[nf >> 1][(nf & 1) * 2], bfr[nf >> 1][(nf & 1) * 2 + 1]);
        }

        // add shifted position scores (smem), mask, scale, online softmax
        float mnew0 = mrow0, mnew1 = mrow1;
#pragma unroll
        for (int nf = 0; nf < 8; ++nf) {
            int jc = j0 + nf * 8 + c0l;
            uint32_t u0 = sS2[s * 4096 + lr0 * 32 + ((nf ^ r0l) << 2) + (lane & 3)];
            uint32_t u1 = sS2[s * 4096 + lr1 * 32 + ((nf ^ r0l) << 2) + (lane & 3)];
            float2 p0 = __half22float2(*reinterpret_cast<__half2*>(&u0));
            float2 p1 = __half22float2(*reinterpret_cast<__half2*>(&u1));
            float s00 = (sacc[nf][0] + p0.x) * SCALE;
            float s01 = (sacc[nf][1] + p0.y) * SCALE;
            float s10 = (sacc[nf][2] + p1.x) * SCALE;
            float s11 = (sacc[nf][3] + p1.y) * SCALE;
            sacc[nf][0] = (jc     <= gi0 + 512) ? s00 : -1e30f;
            sacc[nf][1] = (jc + 1 <= gi0 + 512) ? s01 : -1e30f;
            sacc[nf][2] = (jc     <= gi1 + 512) ? s10 : -1e30f;
            sacc[nf][3] = (jc + 1 <= gi1 + 512) ? s11 : -1e30f;
            mnew0 = fmaxf(mnew0, fmaxf(sacc[nf][0], sacc[nf][1]));
            mnew1 = fmaxf(mnew1, fmaxf(sacc[nf][2], sacc[nf][3]));
        }
#pragma unroll
        for (int d = 1; d < 4; d <<= 1) {
            mnew0 = fmaxf(mnew0, __shfl_xor_sync(0xffffffffu, mnew0, d));
            mnew1 = fmaxf(mnew1, __shfl_xor_sync(0xffffffffu, mnew1, d));
        }
        float fs0 = __expf(mrow0 - mnew0);
        float fs1 = __expf(mrow1 - mnew1);
        mrow0 = mnew0; mrow1 = mnew1;
        float ps0 = 0.f, ps1 = 0.f;
#pragma unroll
        for (int nf = 0; nf < 8; ++nf) {
            sacc[nf][0] = __expf(sacc[nf][0] - mnew0);
            sacc[nf][1] = __expf(sacc[nf][1] - mnew0);
            sacc[nf][2] = __expf(sacc[nf][2] - mnew1);
            sacc[nf][3] = __expf(sacc[nf][3] - mnew1);
            ps0 += sacc[nf][0] + sacc[nf][1];
            ps1 += sacc[nf][2] + sacc[nf][3];
        }
#pragma unroll
        for (int d = 1; d < 4; d <<= 1) {
            ps0 += __shfl_xor_sync(0xffffffffu, ps0, d);
            ps1 += __shfl_xor_sync(0xffffffffu, ps1, d);
        }
        lrow0 = lrow0 * fs0 + ps0;
        lrow1 = lrow1 * fs1 + ps1;
#pragma unroll
        for (int nf = 0; nf < 16; ++nf) {
            of[nf][0] *= fs0; of[nf][1] *= fs0;
            of[nf][2] *= fs1; of[nf][3] *= fs1;
        }

        // store P to warp-private sP rows (fp16 pairs, swizzled)
#pragma unroll
        for (int nf = 0; nf < 8; ++nf) {
            int c  = nf * 8 + c0l;
            int ch = c >> 3, wi = (c >> 1) & 3;
            int row0 = w * 16 + r0l;
            sP[row0 * 32 + ((ch ^ (row0 & 7)) << 2) + wi] = f2h2(sacc[nf][0], sacc[nf][1]);
            int row1 = row0 + 8;
            sP[row1 * 32 + ((ch ^ (row1 & 7)) << 2) + wi] = f2h2(sacc[nf][2], sacc[nf][3]);
        }
        __syncwarp();

        // O += P V^T
#pragma unroll
        for (int ks = 0; ks < 4; ++ks) {
            uint32_t pa[4];
            {
                int row = w * 16 + ((lm & 1) << 3) + lrow;
                int ch  = ks * 2 + (lm >> 1);
                ldsm4(pa[0], pa[1], pa[2], pa[3],
                      sPb + ((row * 32 + ((ch ^ lrow) << 2)) << 2));
            }
#pragma unroll
            for (int nb = 0; nb < 8; ++nb) {
                uint32_t bv[4];
                int rowb = nb * 16 + ((lm >> 1) << 3) + lrow;
                int chb  = ks * 2 + (lm & 1);
                ldsm4(bv[0], bv[1], bv[2], bv[3],
                      sVb + ((s * 4096 + rowb * 32 + ((chb ^ lrow) << 2)) << 2));
                mma16(of[nb * 2],     pa, bv[0], bv[1]);
                mma16(of[nb * 2 + 1], pa, bv[2], bv[3]);
            }
        }
        __syncthreads();
    }

    // normalize + write O (fp16)
    float inv0 = 1.f / lrow0, inv1 = 1.f / lrow1;
    int b = bh >> 3, h = bh & 7;
#pragma unroll
    for (int nf = 0; nf < 16; ++nf) {
        int d = nf * 8 + c0l;
        *(uint32_t*)&g_O[(size_t)(gi0 * 16 + b) * 1024 + h * 128 + d] = f2h2(of[nf][0] * inv0, of[nf][1] * inv0);
        *(uint32_t*)&g_O[(size_t)(gi1 * 16 + b) * 1024 + h * 128 + d] = f2h2(of[nf][2] * inv1, of[nf][3] * inv1);
    }
}

__global__ void copy_k(const float* __restrict__ src, float* __restrict__ dst) {
    int idx = blockIdx.x * blockDim.x + threadIdx.x;
    ((float4*)dst)[idx] = ((const float4*)src)[idx];
}

extern "C" void kernel_launch(void* const* d_in, const int* in_sizes, int n_in,
                              void* d_out, int out_size) {
    const float* inputs = (const float*)d_in[0];
    const float* memory = (const float*)d_in[1];
    const float* w_kv   = (const float*)d_in[2];
    const float* w_q    = (const float*)d_in[3];
    const float* w_p    = (const float*)d_in[4];
    const float* w_out  = (const float*)d_in[5];
    const float* u      = (const float*)d_in[6];
    const float* v      = (const float*)d_in[7];
    float* out = (float*)d_out;

    int writeAux = (out_size >= 3 * 1048576) ? 1 : 0;

    cudaFuncSetAttribute(flash_k, cudaFuncAttributeMaxDynamicSharedMemorySize, 114688);

    pe_fill<<<256, 256>>>();
    // kv proj: M=16384, N=2048, K=128
    gemm_k<0><<<dim3(32, 128, 1), 256>>>(inputs, memory, w_kv, nullptr, nullptr, nullptr, 0);
    // q proj: M=8192, N=1024, K=128
    gemm_k<1><<<dim3(16, 64, 1), 256>>>(inputs, nullptr, w_q, u, v, nullptr, 0);
    // p proj: M=1024, N=1024, K=128
    gemm_k<2><<<dim3(16, 8, 1), 256>>>(inputs, nullptr, w_p, nullptr, nullptr, nullptr, 0);
    // position scores (shifted epilogue): M=512, N=1024, K=128, z=128
    gemm_k<4><<<dim3(16, 4, 128), 256>>>(inputs, nullptr, nullptr, nullptr, nullptr, nullptr, 0);
    // fused flash attention (double-buffered cp.async)
    flash_k<<<dim3(4, 128), 256, 114688>>>();
    // out proj: M=8192, N=128, K=1024
    gemm_k<6><<<dim3(2, 64), 256>>>(inputs, nullptr, w_out, nullptr, nullptr, out, writeAux);
    if (writeAux) copy_k<<<1024, 256>>>(inputs, out + 1048576);
}

// round 11
// speedup vs baseline: 1.0885x; 1.0362x over previous
#include <cuda_runtime.h>
#include <cuda_fp16.h>
#include <math.h>
#include <stdint.h>

#define SCALE 0.088388347648318447f  // 1/sqrt(128)

// ---- static scratch (allocation-free), fp16 intermediates ----
__device__ __half g_K  [16777216];   // [b,h,j,d]
__device__ __half g_Vt [16777216];   // [b,h,d,j]
__device__ __half g_QU [8388608];    // [b,h,i,d]  q+u
__device__ __half g_QV [8388608];    // [b,h,i,d]  q+v
__device__ __half g_P  [1048576];    // [h,jj,d]
__device__ __half g_S2 [67108864];   // [bh,i,j]   shifted position scores (valid j<=i+512)
__device__ __half g_O  [8388608];    // [i*B+b, h*128+d]
__device__ float  g_PE [131072];     // [jj,e]

__global__ void pe_fill() {
    int idx = blockIdx.x * blockDim.x + threadIdx.x;
    if (idx >= 65536) return;
    int jj = idx >> 6, e2 = idx & 63;
    double pos  = (double)(1023 - jj);
    double invf = exp(-((double)e2 / 64.0) * log(10000.0));
    double ang  = pos * invf;
    g_PE[jj * 128 + e2]      = (float)sin(ang);
    g_PE[jj * 128 + 64 + e2] = (float)cos(ang);
}

__device__ __forceinline__ uint32_t f2h2(float a, float b) {
    __half2 h = __floats2half2_rn(a, b);
    return *reinterpret_cast<uint32_t*>(&h);
}
__device__ __forceinline__ void ldsm4(uint32_t& r0, uint32_t& r1, uint32_t& r2, uint32_t& r3, uint32_t addr) {
    asm volatile("ldmatrix.sync.aligned.m8n8.x4.shared.b16 {%0,%1,%2,%3}, [%4];"
                 : "=r"(r0), "=r"(r1), "=r"(r2), "=r"(r3) : "r"(addr));
}
__device__ __forceinline__ void mma16(float* c, const uint32_t* a, uint32_t b0, uint32_t b1) {
    asm volatile("mma.sync.aligned.m16n8k16.row.col.f32.f16.f16.f32 "
                 "{%0,%1,%2,%3},{%4,%5,%6,%7},{%8,%9},{%0,%1,%2,%3};"
                 : "+f"(c[0]), "+f"(c[1]), "+f"(c[2]), "+f"(c[3])
                 : "r"(a[0]), "r"(a[1]), "r"(a[2]), "r"(a[3]), "r"(b0), "r"(b1));
}
__device__ __forceinline__ void cpa16(uint32_t saddr, const void* gptr) {
    asm volatile("cp.async.cg.shared.global [%0], [%1], 16;" :: "r"(saddr), "l"(gptr));
}
__device__ __forceinline__ void cp_commit() { asm volatile("cp.async.commit_group;"); }
template<int N> __device__ __forceinline__ void cp_wait() { asm volatile("cp.async.wait_group %0;" :: "n"(N)); }

// ---- fp16 tensor-core NT GEMM: C[M,N] = A[M,K] * W[N,K]^T ----
// BM=128, BN=64, BK=64 halves; 8 warps, each 32x32 via m16n8k16.
// Double-buffered smem, ONE barrier per K-iter.
// MODE 0: kv proj  1: q proj  2: p proj  4: pos scores (rel-shift epilogue)  6: out proj
template<int MODE>
__global__ void __launch_bounds__(256, 2) gemm_k(
    const float* __restrict__ inputs, const float* __restrict__ mem0,
    const float* __restrict__ Wext, const float* __restrict__ uu,
    const float* __restrict__ vv, float* __restrict__ dout, int writeAux)
{
    constexpr int K   = (MODE >= 5) ? 1024 : 128;  // elements
    constexpr int KIT = K / 64;
    constexpr bool AF32 = (MODE <= 2);
    constexpr bool BF32 = (MODE <= 2 || MODE == 6);
    const int z  = blockIdx.z;
    const int m0 = blockIdx.y * 128, n0 = blockIdx.x * 64;
    if (MODE == 4 && m0 + n0 + 190 < 511) return;  // fully outside used band
    const int tid = threadIdx.x;
    const int lane = tid & 31, w = tid >> 5;
    const int wm = w >> 1, wn = w & 1;

    const float* Af = nullptr;
    const __half* Ah = nullptr;
    const float* Bf = Wext;
    const __half* Bh = nullptr;
    if (MODE == 1) Af = inputs;
    if (MODE == 2) Af = g_PE;
    if (MODE == 4) { Ah = g_QV + (size_t)z * 65536;  Bh = g_P + (size_t)(z & 7) * 131072; }
    if (MODE == 6) { Ah = g_O; }

    __shared__ uint32_t As[2][4096];
    __shared__ uint32_t Bs[2][2048];
    uint32_t as_addr = (uint32_t)__cvta_generic_to_shared(As);
    uint32_t bs_addr = (uint32_t)__cvta_generic_to_shared(Bs);

    float acc[2][4][4];
#pragma unroll
    for (int a = 0; a < 2; ++a)
#pragma unroll
        for (int b = 0; b < 4; ++b)
#pragma unroll
            for (int c = 0; c < 4; ++c) acc[a][b][c] = 0.f;

    float4 pa32[4][2], pb32[2][2];
    uint4 pa16[4], pb16[2];

    auto loadA = [&](int it) {
#pragma unroll
        for (int i = 0; i < 4; ++i) {
            int idx = tid + i * 256;
            int row = idx >> 3, ch = idx & 7;
            int r = m0 + row;
            if (AF32) {
                const float* Ap;
                if (MODE == 0)
                    Ap = (r < 8192) ? (mem0 + (size_t)r * 128)
                                    : (inputs + (size_t)(r - 8192) * 128);
                else
                    Ap = Af + (size_t)r * K;
                pa32[i][0] = *(const float4*)(Ap + it * 64 + ch * 8);
                pa32[i][1] = *(const float4*)(Ap + it * 64 + ch * 8 + 4);
            } else {
                pa16[i] = *(const uint4*)(Ah + (size_t)r * K + it * 64 + ch * 8);
            }
        }
    };
    auto loadB = [&](int it) {
#pragma unroll
        for (int i = 0; i < 2; ++i) {
            int idx = tid + i * 256;
            int row = idx >> 3, ch = idx & 7;
            if (BF32) {
                pb32[i][0] = *(const float4*)(Bf + (size_t)(n0 + row) * K + it * 64 + ch * 8);
                pb32[i][1] = *(const float4*)(Bf + (size_t)(n0 + row) * K + it * 64 + ch * 8 + 4);
            } else {
                pb16[i] = *(const uint4*)(Bh + (size_t)(n0 + row) * K + it * 64 + ch * 8);
            }
        }
    };
    auto stage = [&](int s) {
#pragma unroll
        for (int i = 0; i < 4; ++i) {
            int idx = tid + i * 256;
            int row = idx >> 3, ch = idx & 7;
            uint32_t off = row * 32 + ((ch ^ (row & 7)) << 2);
            uint4 v;
            if (AF32) v = make_uint4(f2h2(pa32[i][0].x, pa32[i][0].y), f2h2(pa32[i][0].z, pa32[i][0].w),
                                     f2h2(pa32[i][1].x, pa32[i][1].y), f2h2(pa32[i][1].z, pa32[i][1].w));
            else v = pa16[i];
            *(uint4*)&As[s][off] = v;
        }
#pragma unroll
        for (int i = 0; i < 2; ++i) {
            int idx = tid + i * 256;
            int row = idx >> 3, ch = idx & 7;
            uint32_t off = row * 32 + ((ch ^ (row & 7)) << 2);
            uint4 v;
            if (BF32) v = make_uint4(f2h2(pb32[i][0].x, pb32[i][0].y), f2h2(pb32[i][0].z, pb32[i][0].w),
                                     f2h2(pb32[i][1].x, pb32[i][1].y), f2h2(pb32[i][1].z, pb32[i][1].w));
            else v = pb16[i];
            *(uint4*)&Bs[s][off] = v;
        }
    };

    loadA(0); loadB(0);
    stage(0);
    __syncthreads();

    const int lrow = lane & 7, lm = lane >> 3;
    for (int it = 0; it < KIT; ++it) {
        const int s = it & 1;
        if (it + 1 < KIT) { loadA(it + 1); loadB(it + 1); }
#pragma unroll
        for (int ks = 0; ks < 4; ++ks) {  // k16 steps within BK=64
            uint32_t afr[2][4], bfr[2][4];
#pragma unroll
            for (int mi = 0; mi < 2; ++mi) {
                int row = wm * 32 + mi * 16 + ((lm & 1) << 3) + lrow;
                int ch  = ks * 2 + (lm >> 1);
                ldsm4(afr[mi][0], afr[mi][1], afr[mi][2], afr[mi][3],
                      as_addr + ((s * 4096 + row * 32 + ((ch ^ lrow) << 2)) << 2));
            }
#pragma unroll
            for (int np = 0; np < 2; ++np) {
                int row = wn * 32 + np * 16 + ((lm >> 1) << 3) + lrow;
                int ch  = ks * 2 + (lm & 1);
                ldsm4(bfr[np][0], bfr[np][1], bfr[np][2], bfr[np][3],
                      bs_addr + ((s * 2048 + row * 32 + ((ch ^ lrow) << 2)) << 2));
            }
#pragma unroll
            for (int mi = 0; mi < 2; ++mi)
#pragma unroll
                for (int nj = 0; nj < 4; ++nj)
                    mma16(acc[mi][nj], afr[mi], bfr[nj >> 1][(nj & 1) * 2], bfr[nj >> 1][(nj & 1) * 2 + 1]);
        }
        if (it + 1 < KIT) { stage(s ^ 1); __syncthreads(); }
    }

    // ---- epilogue ----
    const int r0l = lane >> 2, c0l = (lane & 3) * 2;
#pragma unroll
    for (int mi = 0; mi < 2; ++mi)
#pragma unroll
        for (int nj = 0; nj < 4; ++nj)
#pragma unroll
            for (int e = 0; e < 4; ++e) {
                int r = m0 + wm * 32 + mi * 16 + r0l + ((e >= 2) ? 8 : 0);
                int n = n0 + wn * 32 + nj * 8 + c0l + (e & 1);
                float val = acc[mi][nj][e];
                if (MODE == 0) {
                    int j = r >> 4, b = r & 15;
                    if (n < 1024) {
                        int h = n >> 7, d = n & 127;
                        g_K[(size_t)((b * 8 + h) * 1024 + j) * 128 + d] = __float2half(val);
                    } else {
                        int n2 = n - 1024; int h = n2 >> 7, d = n2 & 127;
                        g_Vt[(size_t)((b * 8 + h) * 128 + d) * 1024 + j] = __float2half(val);
                    }
                } else if (MODE == 1) {
                    int i = r >> 4, b = r & 15;
                    size_t base = (size_t)((b * 8 + (n >> 7)) * 512 + i) * 128 + (n & 127);
                    g_QU[base] = __float2half(val + uu[n]);
                    g_QV[base] = __float2half(val + vv[n]);
                } else if (MODE == 2) {
                    g_P[(size_t)((n >> 7) * 1024 + r) * 128 + (n & 127)] = __float2half(val);
                } else if (MODE == 4) {
                    int j = n - 511 + r;  // rel-shift: S2shift[i][j] = S2[i][511+j-i]
                    if (j >= 0 && j < 1024)
                        g_S2[(size_t)z * 524288 + (size_t)r * 1024 + j] = __float2half(val);
                } else {  // MODE 6
                    dout[(size_t)r * 128 + n] = val;
                    if (writeAux) dout[2097152 + (size_t)r * 128 + n] = val;
                }
            }
}

// ---- fused flash attention (fp16): 64-row CTAs, 128 threads, 2 CTAs/SM ----
// S = QK^T + S2shift, masked online softmax, O = P V.
// K, V, S2 tiles double-buffered via cp.async: jt+1 loads overlap jt compute.
// Per stage (10240 u32): K at +0 (2 segs x 2048), V at +4096, S2 at +8192 (64 rows).
__global__ void __launch_bounds__(128, 2) flash_k() {
    extern __shared__ uint32_t sm[];
    uint32_t* sP = sm + 20480;     // 64 i-rows x 32 u32
    const uint32_t smb = (uint32_t)__cvta_generic_to_shared(sm);
    const uint32_t sPb = (uint32_t)__cvta_generic_to_shared(sP);

    const int bh = blockIdx.y;
    const int ix = 7 - blockIdx.x;     // heavy tiles launch first
    const int i0 = ix * 64;
    const int tid = threadIdx.x, lane = tid & 31, w = tid >> 5;  // w in 0..3
    const int lrow = lane & 7, lm = lane >> 3;
    const int r0l = lane >> 2, c0l = (lane & 3) * 2;

    const __half* Qb  = g_QU + (size_t)bh * 65536;
    const __half* Kb  = g_K  + (size_t)bh * 131072;
    const __half* Vb  = g_Vt + (size_t)bh * 131072;
    const __half* S2b = g_S2 + (size_t)bh * 524288;

    uint32_t qf[8][4];

    // ---- Q fragments via smem staging (single 64-row pass into stage-0 K region) ----
#pragma unroll
    for (int t = 0; t < 8; ++t) {
        int idx = tid + t * 128;
        int row = idx >> 4, c16 = idx & 15;
        int seg = c16 >> 3, ch = c16 & 7;
        uint4 v = *(const uint4*)(Qb + (size_t)(i0 + row) * 128 + c16 * 8);
        *(uint4*)&sm[seg * 2048 + row * 32 + ((ch ^ (row & 7)) << 2)] = v;
    }
    __syncthreads();
    {
        int wr = w * 16;
#pragma unroll
        for (int ks = 0; ks < 8; ++ks) {
            int row = wr + ((lm & 1) << 3) + lrow;
            int seg = ks >> 2, ch = (ks & 3) * 2 + (lm >> 1);
            ldsm4(qf[ks][0], qf[ks][1], qf[ks][2], qf[ks][3],
                  smb + ((seg * 2048 + row * 32 + ((ch ^ lrow) << 2)) << 2));
        }
    }
    __syncthreads();

    // cp.async prefetch of one jt tile (K 16KB + V 16KB + S2 8KB) into stage s
    auto pref = [&](int jt, int s) {
        int j0 = jt * 64;
        int sb = s * 10240;
#pragma unroll
        for (int t = 0; t < 8; ++t) {
            int idx = tid + t * 128;
            int row = idx >> 4, c16 = idx & 15;
            int seg = c16 >> 3, ch = c16 & 7;
            cpa16(smb + ((sb + seg * 2048 + row * 32 + ((ch ^ (row & 7)) << 2)) << 2),
                  Kb + (size_t)(j0 + row) * 128 + c16 * 8);
        }
#pragma unroll
        for (int t = 0; t < 8; ++t) {
            int idx = tid + t * 128;
            int row = idx >> 3, ch = idx & 7;
            cpa16(smb + ((sb + 4096 + row * 32 + ((ch ^ (row & 7)) << 2)) << 2),
                  Vb + (size_t)row * 1024 + j0 + ch * 8);
        }
#pragma unroll
        for (int t = 0; t < 4; ++t) {
            int idx = tid + t * 128;
            int row = idx >> 3, ch = idx & 7;
            cpa16(smb + ((sb + 8192 + row * 32 + ((ch ^ (row & 7)) << 2)) << 2),
                  S2b + (size_t)(i0 + row) * 1024 + j0 + ch * 8);
        }
    };

    float of[16][4];
#pragma unroll
    for (int a = 0; a < 16; ++a)
#pragma unroll
        for (int e = 0; e < 4; ++e) of[a][e] = 0.f;
    float mrow0 = -1e30f, mrow1 = -1e30f;
    float lrow0 = 0.f, lrow1 = 0.f;

    const int gi0 = i0 + w * 16 + r0l;
    const int gi1 = gi0 + 8;
    const int lr0 = w * 16 + r0l, lr1 = lr0 + 8;  // local rows in sS2/sP (0..63)
    const int njt = ix + 9;       // covers j <= i0+63+512

    pref(0, 0); cp_commit();

    for (int jt = 0; jt < njt; ++jt) {
        const int s = jt & 1;
        int j0 = jt * 64;
        if (jt + 1 < njt) { pref(jt + 1, s ^ 1); cp_commit(); cp_wait<1>(); }
        else cp_wait<0>();
        __syncthreads();
        const int sb = s * 10240;

        // scores: S = Q K^T (16 x 64 per warp)
        float sacc[8][4];
#pragma unroll
        for (int a = 0; a < 8; ++a)
#pragma unroll
            for (int e = 0; e < 4; ++e) sacc[a][e] = 0.f;
#pragma unroll
        for (int ks = 0; ks < 8; ++ks) {
            uint32_t bfr[4][4];
#pragma unroll
            for (int nb = 0; nb < 4; ++nb) {
                int row = nb * 16 + ((lm >> 1) << 3) + lrow;
                int seg = ks >> 2, ch = (ks & 3) * 2 + (lm & 1);
                ldsm4(bfr[nb][0], bfr[nb][1], bfr[nb][2], bfr[nb][3],
                      smb + ((sb + seg * 2048 + row * 32 + ((ch ^ lrow) << 2)) << 2));
            }
#pragma unroll
            for (int nf = 0; nf < 8; ++nf)
                mma16(sacc[nf], qf[ks], bfr[nf >> 1][(nf & 1) * 2], bfr[nf >> 1][(nf & 1) * 2 + 1]);
        }

        // add shifted position scores (smem), mask, scale, online softmax
        float mnew0 = mrow0, mnew1 = mrow1;
#pragma unroll
        for (int nf = 0; nf < 8; ++nf) {
            int jc = j0 + nf * 8 + c0l;
            uint32_t u0 = sm[sb + 8192 + lr0 * 32 + ((nf ^ r0l) << 2) + (lane & 3)];
            uint32_t u1 = sm[sb + 8192 + lr1 * 32 + ((nf ^ r0l) << 2) + (lane & 3)];
            float2 p0 = __half22float2(*reinterpret_cast<__half2*>(&u0));
            float2 p1 = __half22float2(*reinterpret_cast<__half2*>(&u1));
            float s00 = (sacc[nf][0] + p0.x) * SCALE;
            float s01 = (sacc[nf][1] + p0.y) * SCALE;
            float s10 = (sacc[nf][2] + p1.x) * SCALE;
            float s11 = (sacc[nf][3] + p1.y) * SCALE;
            sacc[nf][0] = (jc     <= gi0 + 512) ? s00 : -1e30f;
            sacc[nf][1] = (jc + 1 <= gi0 + 512) ? s01 : -1e30f;
            sacc[nf][2] = (jc     <= gi1 + 512) ? s10 : -1e30f;
            sacc[nf][3] = (jc + 1 <= gi1 + 512) ? s11 : -1e30f;
            mnew0 = fmaxf(mnew0, fmaxf(sacc[nf][0], sacc[nf][1]));
            mnew1 = fmaxf(mnew1, fmaxf(sacc[nf][2], sacc[nf][3]));
        }
#pragma unroll
        for (int d = 1; d < 4; d <<= 1) {
            mnew0 = fmaxf(mnew0, __shfl_xor_sync(0xffffffffu, mnew0, d));
            mnew1 = fmaxf(mnew1, __shfl_xor_sync(0xffffffffu, mnew1, d));
        }
        float fs0 = __expf(mrow0 - mnew0);
        float fs1 = __expf(mrow1 - mnew1);
        mrow0 = mnew0; mrow1 = mnew1;
        float ps0 = 0.f, ps1 = 0.f;
#pragma unroll
        for (int nf = 0; nf < 8; ++nf) {
            sacc[nf][0] = __expf(sacc[nf][0] - mnew0);
            sacc[nf][1] = __expf(sacc[nf][1] - mnew0);
            sacc[nf][2] = __expf(sacc[nf][2] - mnew1);
            sacc[nf][3] = __expf(sacc[nf][3] - mnew1);
            ps0 += sacc[nf][0] + sacc[nf][1];
            ps1 += sacc[nf][2] + sacc[nf][3];
        }
#pragma unroll
        for (int d = 1; d < 4; d <<= 1) {
            ps0 += __shfl_xor_sync(0xffffffffu, ps0, d);
            ps1 += __shfl_xor_sync(0xffffffffu, ps1, d);
        }
        lrow0 = lrow0 * fs0 + ps0;
        lrow1 = lrow1 * fs1 + ps1;
#pragma unroll
        for (int nf = 0; nf < 16; ++nf) {
            of[nf][0] *= fs0; of[nf][1] *= fs0;
            of[nf][2] *= fs1; of[nf][3] *= fs1;
        }

        // store P to warp-private sP rows (fp16 pairs, swizzled)
#pragma unroll
        for (int nf = 0; nf < 8; ++nf) {
            int c  = nf * 8 + c0l;
            int ch = c >> 3, wi = (c >> 1) & 3;
            int row0 = w * 16 + r0l;
            sP[row0 * 32 + ((ch ^ (row0 & 7)) << 2) + wi] = f2h2(sacc[nf][0], sacc[nf][1]);
            int row1 = row0 + 8;
            sP[row1 * 32 + ((ch ^ (row1 & 7)) << 2) + wi] = f2h2(sacc[nf][2], sacc[nf][3]);
        }
        __syncwarp();

        // O += P V^T
#pragma unroll
        for (int ks = 0; ks < 4; ++ks) {
            uint32_t pa[4];
            {
                int row = w * 16 + ((lm & 1) << 3) + lrow;
                int ch  = ks * 2 + (lm >> 1);
                ldsm4(pa[0], pa[1], pa[2], pa[3],
                      sPb + ((row * 32 + ((ch ^ lrow) << 2)) << 2));
            }
#pragma unroll
            for (int nb = 0; nb < 8; ++nb) {
                uint32_t bv[4];
                int rowb = nb * 16 + ((lm >> 1) << 3) + lrow;
                int chb  = ks * 2 + (lm & 1);
                ldsm4(bv[0], bv[1], bv[2], bv[3],
                      smb + ((sb + 4096 + rowb * 32 + ((chb ^ lrow) << 2)) << 2));
                mma16(of[nb * 2],     pa, bv[0], bv[1]);
                mma16(of[nb * 2 + 1], pa, bv[2], bv[3]);
            }
        }
        __syncthreads();
    }

    // normalize + write O (fp16)
    float inv0 = 1.f / lrow0, inv1 = 1.f / lrow1;
    int b = bh >> 3, h = bh & 7;
#pragma unroll
    for (int nf = 0; nf < 16; ++nf) {
        int d = nf * 8 + c0l;
        *(uint32_t*)&g_O[(size_t)(gi0 * 16 + b) * 1024 + h * 128 + d] = f2h2(of[nf][0] * inv0, of[nf][1] * inv0);
        *(uint32_t*)&g_O[(size_t)(gi1 * 16 + b) * 1024 + h * 128 + d] = f2h2(of[nf][2] * inv1, of[nf][3] * inv1);
    }
}

__global__ void copy_k(const float* __restrict__ src, float* __restrict__ dst) {
    int idx = blockIdx.x * blockDim.x + threadIdx.x;
    ((float4*)dst)[idx] = ((const float4*)src)[idx];
}

extern "C" void kernel_launch(void* const* d_in, const int* in_sizes, int n_in,
                              void* d_out, int out_size) {
    const float* inputs = (const float*)d_in[0];
    const float* memory = (const float*)d_in[1];
    const float* w_kv   = (const float*)d_in[2];
    const float* w_q    = (const float*)d_in[3];
    const float* w_p    = (const float*)d_in[4];
    const float* w_out  = (const float*)d_in[5];
    const float* u      = (const float*)d_in[6];
    const float* v      = (const float*)d_in[7];
    float* out = (float*)d_out;

    int writeAux = (out_size >= 3 * 1048576) ? 1 : 0;

    // smem: 2 stages x 40KB + sP 8KB = 90112 B
    cudaFuncSetAttribute(flash_k, cudaFuncAttributeMaxDynamicSharedMemorySize, 90112);

    pe_fill<<<256, 256>>>();
    // kv proj: M=16384, N=2048, K=128
    gemm_k<0><<<dim3(32, 128, 1), 256>>>(inputs, memory, w_kv, nullptr, nullptr, nullptr, 0);
    // q proj: M=8192, N=1024, K=128
    gemm_k<1><<<dim3(16, 64, 1), 256>>>(inputs, nullptr, w_q, u, v, nullptr, 0);
    // p proj: M=1024, N=1024, K=128
    gemm_k<2><<<dim3(16, 8, 1), 256>>>(inputs, nullptr, w_p, nullptr, nullptr, nullptr, 0);
    // position scores (shifted epilogue): M=512, N=1024, K=128, z=128
    gemm_k<4><<<dim3(16, 4, 128), 256>>>(inputs, nullptr, nullptr, nullptr, nullptr, nullptr, 0);
    // fused flash attention: 64-row CTAs, 128 threads, 2 CTAs/SM
    flash_k<<<dim3(8, 128), 128, 90112>>>();
    // out proj: M=8192, N=128, K=1024
    gemm_k<6><<<dim3(2, 64), 256>>>(inputs, nullptr, w_out, nullptr, nullptr, out, writeAux);
    if (writeAux) copy_k<<<1024, 256>>>(inputs, out + 1048576);
}